// round 14
// baseline (speedup 1.0000x reference)
#include <cuda_runtime.h>
#include <cuda_fp16.h>
#include <cstdint>

using fp16 = __half;

// Problem constants (fixed by reference)
constexpr int Bb = 4;
constexpr int Nn = 2048;
constexpr int Cc = 1024;
constexpr int Hh = 16;
constexpr int Dd = 64;
constexpr int Mm = Bb * Nn;   // 8192 tokens

// Q pre-scale: 1/sqrt(D) * log2(e)  (softmax done in base-2)
#define SCALE_Q 0.1803368801111204f

// Scratch (allocation-free rule: static device globals)
__device__ fp16 g_x [Mm * Cc];
__device__ fp16 g_q [Mm * Cc];
__device__ fp16 g_k [Mm * Cc];
__device__ fp16 g_v [Mm * Cc];
__device__ fp16 g_o [Mm * Cc];
__device__ fp16 g_wt[4][Cc * Cc];   // W^T [N,K] fp16 (q,k,v contiguous, then o)

// ---------------------------------------------------------------------------
// Portable (sm_100 non-'a') tensor-core helpers
// ---------------------------------------------------------------------------
__device__ __forceinline__ uint32_t smem_u32(const void* p) {
    uint32_t a;
    asm("{ .reg .u64 t; cvta.to.shared.u64 t, %1; cvt.u32.u64 %0, t; }"
        : "=r"(a) : "l"(p));
    return a;
}

__device__ __forceinline__ void mma16816(float* c, const uint32_t* a, const uint32_t* b) {
    asm volatile(
        "mma.sync.aligned.m16n8k16.row.col.f32.f16.f16.f32 "
        "{%0,%1,%2,%3}, {%4,%5,%6,%7}, {%8,%9}, {%0,%1,%2,%3};"
        : "+f"(c[0]), "+f"(c[1]), "+f"(c[2]), "+f"(c[3])
        : "r"(a[0]), "r"(a[1]), "r"(a[2]), "r"(a[3]), "r"(b[0]), "r"(b[1]));
}

__device__ __forceinline__ void ldsm4(uint32_t* r, uint32_t addr) {
    asm volatile("ldmatrix.sync.aligned.m8n8.x4.shared.b16 {%0,%1,%2,%3}, [%4];"
                 : "=r"(r[0]), "=r"(r[1]), "=r"(r[2]), "=r"(r[3]) : "r"(addr));
}

__device__ __forceinline__ void ldsm4t(uint32_t* r, uint32_t addr) {
    asm volatile("ldmatrix.sync.aligned.m8n8.x4.trans.shared.b16 {%0,%1,%2,%3}, [%4];"
                 : "=r"(r[0]), "=r"(r[1]), "=r"(r[2]), "=r"(r[3]) : "r"(addr));
}

__device__ __forceinline__ void cp16(uint32_t dst, const void* src) {
    asm volatile("cp.async.cg.shared.global [%0], [%1], 16;" :: "r"(dst), "l"(src));
}
#define CP_COMMIT() asm volatile("cp.async.commit_group;" ::: "memory")
#define CP_WAIT(n)  asm volatile("cp.async.wait_group %0;" :: "n"(n) : "memory")

__device__ __forceinline__ uint32_t pack2h(float a, float b) {
    __half2 t = __floats2half2_rn(a, b);
    return *(uint32_t*)&t;
}

// ---------------------------------------------------------------------------
// Conversion kernels
// ---------------------------------------------------------------------------
// x fp32 -> fp16, grid-stride with 4 independent float4s/thread (MLP=4).
__global__ void conv_h(const float* __restrict__ in, fp16* __restrict__ out, int n4) {
    const int i0 = blockIdx.x * blockDim.x + threadIdx.x;
    const int stride = gridDim.x * blockDim.x;
    #pragma unroll
    for (int j = 0; j < 4; j++) {
        const int idx = i0 + j * stride;
        if (idx < n4) {
            float4 v = ((const float4*)in)[idx];
            ((uint32_t*)out)[idx * 2    ] = pack2h(v.x, v.y);
            ((uint32_t*)out)[idx * 2 + 1] = pack2h(v.z, v.w);
        }
    }
}

// All four W [K,N] -> WT [N,K] fp16 in ONE launch (blockIdx.z selects matrix).
struct W4 { const float* w[4]; };
__global__ void conv_wt4(W4 ws, fp16* __restrict__ th_base) {
    __shared__ float t[32][33];
    const float* W = ws.w[blockIdx.z];
    fp16* th = th_base + (size_t)blockIdx.z * Cc * Cc;
    const int bx = blockIdx.x, by = blockIdx.y;
    const int tx = threadIdx.x, ty0 = threadIdx.y;  // 32 x 8
    #pragma unroll
    for (int i = 0; i < 32; i += 8)
        t[ty0 + i][tx] = W[(size_t)(by * 32 + ty0 + i) * Cc + bx * 32 + tx];
    __syncthreads();
    #pragma unroll
    for (int i = 0; i < 32; i += 8) {
        float v = t[tx][ty0 + i];
        th[(size_t)(bx * 32 + ty0 + i) * Cc + by * 32 + tx] = __float2half_rn(v);
    }
}

// ---------------------------------------------------------------------------
// GEMM tiling constants (shared by both GEMM kernels)
// CTA tile 128x256, K-chunk 64, 2-stage cp.async double buffer, 8 warps.
// Rows: 64 fp16 = 128B; 16B-unit swizzle u^(row&7).
// ---------------------------------------------------------------------------
constexpr int KC        = 64;
constexpr int NCHUNK    = Cc / KC;        // 16
constexpr int A_TILE_B  = 128 * 128;      // 16KB
constexpr int B_TILE_B  = 256 * 128;      // 32KB
constexpr int STAGE_B   = A_TILE_B + B_TILE_B;   // 49152
constexpr int GEMM_SMEM = 2 * STAGE_B;    // 98304

#define GEMM_MAINLOOP(Aptr, Bptr)                                              \
    const int r0 = tid >> 3, u = tid & 7;                                      \
    const uint32_t du = (uint32_t)((u ^ (r0 & 7)) << 4);                       \
    const fp16* aPb = (Aptr) + (size_t)(m0 + r0) * Cc + u * 8;                 \
    const fp16* bPb = (Bptr) + (size_t)(n0 + r0) * Cc + u * 8;                 \
    const uint32_t aDb = (uint32_t)(r0 * 128) + du;                            \
    const uint32_t bDb = (uint32_t)(A_TILE_B + r0 * 128) + du;                 \
    const int r7  = lane & 7;                                                  \
    const int auh = lane >> 4;                                                 \
    const int buh = (lane >> 3) & 1;                                           \
    uint32_t aoff[4], boff[4];                                                 \
    _Pragma("unroll")                                                          \
    for (int mi = 0; mi < 4; mi++)                                             \
        aoff[mi] = (uint32_t)((wm * 64 + mi * 16 + (lane & 15)) * 128);        \
    _Pragma("unroll")                                                          \
    for (int pi = 0; pi < 4; pi++)                                             \
        boff[pi] = (uint32_t)(A_TILE_B +                                       \
            (wn * 64 + pi * 16 + ((lane >> 4) << 3) + (lane & 7)) * 128);      \
    float acc[4][8][4];                                                        \
    _Pragma("unroll")                                                          \
    for (int mi = 0; mi < 4; mi++)                                             \
        _Pragma("unroll")                                                      \
        for (int ni = 0; ni < 8; ni++)                                         \
            _Pragma("unroll")                                                  \
            for (int k = 0; k < 4; k++) acc[mi][ni][k] = 0.0f;                 \
    auto load_chunk = [&](int c, int s) {                                      \
        const uint32_t stg = sbase + (uint32_t)(s * STAGE_B);                  \
        const int koff = c * KC;                                               \
        const fp16* ap = aPb + koff;                                           \
        _Pragma("unroll")                                                      \
        for (int i = 0; i < 4; i++)                                            \
            cp16(stg + aDb + (uint32_t)(i * 4096), ap + (size_t)i * 32 * Cc);  \
        const fp16* bp = bPb + koff;                                           \
        _Pragma("unroll")                                                      \
        for (int i = 0; i < 8; i++)                                            \
            cp16(stg + bDb + (uint32_t)(i * 4096), bp + (size_t)i * 32 * Cc);  \
    };                                                                         \
    load_chunk(0, 0); CP_COMMIT();                                             \
    for (int c = 0; c < NCHUNK; c++) {                                         \
        const int s = c & 1;                                                   \
        if (c + 1 < NCHUNK) {                                                  \
            load_chunk(c + 1, s ^ 1);                                          \
            CP_COMMIT();                                                       \
            CP_WAIT(1);                                                        \
        } else {                                                               \
            CP_WAIT(0);                                                        \
        }                                                                      \
        __syncthreads();                                                       \
        const uint32_t sS = sbase + (uint32_t)(s * STAGE_B);                   \
        _Pragma("unroll")                                                      \
        for (int ks = 0; ks < 4; ks++) {                                       \
            uint32_t a_[4][4], b_[4][4];                                       \
            const uint32_t uh = (uint32_t)(ks << 1);                           \
            _Pragma("unroll")                                                  \
            for (int mi = 0; mi < 4; mi++)                                     \
                ldsm4(a_[mi], sS + aoff[mi] + (((uh + auh) ^ r7) << 4));       \
            _Pragma("unroll")                                                  \
            for (int pi = 0; pi < 4; pi++)                                     \
                ldsm4(b_[pi], sS + boff[pi] + (((uh + buh) ^ r7) << 4));       \
            _Pragma("unroll")                                                  \
            for (int mi = 0; mi < 4; mi++)                                     \
                _Pragma("unroll")                                              \
                for (int ni = 0; ni < 8; ni++)                                 \
                    mma16816(acc[mi][ni], a_[mi], &b_[ni >> 1][(ni & 1) * 2]); \
        }                                                                      \
        __syncthreads();                                                       \
    }

// ---------------------------------------------------------------------------
// Fused QKV projection: one launch, grid (12, 64). B = concatenated
// [Wq^T; Wk^T; Wv^T] (3072 x 1024). Sector (bx>>2) routes output to q/k/v.
// Q is pre-scaled by SCALE_Q (1/sqrt(D) * log2e) for base-2 softmax.
// ---------------------------------------------------------------------------
__global__ __launch_bounds__(256, 1)
void mma_gemm_qkv(const fp16* __restrict__ A, const fp16* __restrict__ B3,
                  const float* __restrict__ bq, const float* __restrict__ bk,
                  const float* __restrict__ bv,
                  fp16* __restrict__ qp, fp16* __restrict__ kp, fp16* __restrict__ vp) {
    extern __shared__ char smem[];
    const uint32_t sbase = smem_u32(smem);
    const int tid  = threadIdx.x;
    const int lane = tid & 31;
    const int wid  = tid >> 5;
    const int m0 = blockIdx.y * 128;
    const int n0 = blockIdx.x * 256;          // global row in [0, 3072)
    const int wm = wid & 1;
    const int wn = wid >> 1;

    const int sector = blockIdx.x >> 2;       // 0=q, 1=k, 2=v
    const int n0l    = n0 & 1023;             // column base within the 1024-wide output
    fp16* OH = (sector == 0) ? qp : (sector == 1) ? kp : vp;
    const float* bias = (sector == 0) ? bq : (sector == 1) ? bk : bv;
    const float scale = (sector == 0) ? SCALE_Q : 1.0f;

    GEMM_MAINLOOP(A, B3)

    // ---- epilogue: + bias, x scale, fp16 out ----
    const int group = lane >> 2, tig = lane & 3;
    #pragma unroll
    for (int mi = 0; mi < 4; mi++) {
        const int r = m0 + wm * 64 + mi * 16 + group;
        #pragma unroll
        for (int ni = 0; ni < 8; ni++) {
            const int col = n0l + wn * 64 + ni * 8 + tig * 2;
            const float b0 = bias[col], b1 = bias[col + 1];
            *(uint32_t*)(OH + (size_t)r * Cc + col) =
                pack2h((acc[mi][ni][0] + b0) * scale, (acc[mi][ni][1] + b1) * scale);
            *(uint32_t*)(OH + (size_t)(r + 8) * Cc + col) =
                pack2h((acc[mi][ni][2] + b0) * scale, (acc[mi][ni][3] + b1) * scale);
        }
    }
}

// ---------------------------------------------------------------------------
// Output projection: fp16 A x fp16 B^T -> fp32 C + bias.
// ---------------------------------------------------------------------------
__global__ __launch_bounds__(256, 1)
void mma_gemm_out(const fp16* __restrict__ A, const fp16* __restrict__ B,
                  const float* __restrict__ bias, float* __restrict__ C) {
    extern __shared__ char smem[];
    const uint32_t sbase = smem_u32(smem);
    const int tid  = threadIdx.x;
    const int lane = tid & 31;
    const int wid  = tid >> 5;
    const int m0 = blockIdx.y * 128;
    const int n0 = blockIdx.x * 256;
    const int wm = wid & 1;
    const int wn = wid >> 1;

    GEMM_MAINLOOP(A, B)

    const int group = lane >> 2, tig = lane & 3;
    #pragma unroll
    for (int mi = 0; mi < 4; mi++) {
        const int r = m0 + wm * 64 + mi * 16 + group;
        #pragma unroll
        for (int ni = 0; ni < 8; ni++) {
            const int col = n0 + wn * 64 + ni * 8 + tig * 2;
            const float b0 = bias[col], b1 = bias[col + 1];
            *(float2*)(C + (size_t)r * Cc + col) =
                make_float2(acc[mi][ni][0] + b0, acc[mi][ni][1] + b1);
            *(float2*)(C + (size_t)(r + 8) * Cc + col) =
                make_float2(acc[mi][ni][2] + b0, acc[mi][ni][3] + b1);
        }
    }
}

// ---------------------------------------------------------------------------
// Tensor-core flash attention, plain fp16 1-term, base-2 softmax (Q carries
// log2e). CTA = 128-row Q tile of one (b,h); 8 warps x 16 S-rows each.
// Smem: Q (16KB) + 2 stages x (K|V) (64KB) = 80KB. Rows 128B, swizzle u^(r&7).
// ---------------------------------------------------------------------------
constexpr int ATT_SMEM = 16384 + 2 * 32768;   // 81920

__global__ __launch_bounds__(256, 1)
void attn_mma(const fp16* __restrict__ Q,
              const fp16* __restrict__ K, const fp16* __restrict__ V) {
    extern __shared__ char smem[];
    const uint32_t sb = smem_u32(smem);
    const int tid  = threadIdx.x;
    const int lane = tid & 31;
    const int wid  = tid >> 5;
    const int bh = blockIdx.y;
    const int b  = bh >> 4;
    const int h  = bh & 15;
    const int q0 = blockIdx.x * 128;
    const size_t tokQ = (size_t)(b * Nn + q0);
    const size_t tokK = (size_t)(b * Nn);
    const int colOff = h * Dd;

    // -- async load Q (one plain tile) --
    #pragma unroll
    for (int i = 0; i < 4; i++) {
        const int idx = tid + i * 256;
        const int r = idx >> 3, u = idx & 7;
        cp16(sb + r * 128 + ((u ^ (r & 7)) << 4),
             Q + (tokQ + r) * Cc + colOff + u * 8);
    }

    auto issue_stage = [&](int t, int s) {
        const uint32_t stg = sb + 16384u + (uint32_t)s * 32768u;
        const size_t tokT = tokK + (size_t)t * 128;
        #pragma unroll
        for (int i = 0; i < 8; i++) {
            const int idx = tid + i * 256;
            const int tile = idx >> 10, rem = idx & 1023;
            const int r = rem >> 3, u = rem & 7;
            const fp16* base = tile ? V : K;
            cp16(stg + tile * 16384 + r * 128 + ((u ^ (r & 7)) << 4),
                 base + (tokT + r) * Cc + colOff + u * 8);
        }
    };

    issue_stage(0, 0); CP_COMMIT();   // group0 = Q + stage0
    issue_stage(1, 1); CP_COMMIT();   // group1 = stage1
    CP_WAIT(1);
    __syncthreads();

    // -- hoist Q fragments (loop-invariant) --
    const int qrow  = wid * 16 + (lane & 15);
    const uint32_t qso = (uint32_t)(qrow * 128);
    uint32_t qf[4][4];
    #pragma unroll
    for (int ks = 0; ks < 4; ks++) {
        const int unit = 2 * ks + (lane >> 4);
        ldsm4(qf[ks], sb + qso + (uint32_t)(((unit ^ (qrow & 7))) << 4));
    }

    float m0 = -1e30f, m1 = -1e30f, l0 = 0.0f, l1 = 0.0f;
    float o[8][4];
    #pragma unroll
    for (int j = 0; j < 8; j++)
        #pragma unroll
        for (int k = 0; k < 4; k++) o[j][k] = 0.0f;

    const int kkey  = ((lane >> 4) << 3) + (lane & 7);
    const int kub   = (lane >> 3) & 1;
    const int vkey0 = lane & 15;
    const int vub   = lane >> 4;

    for (int t = 0; t < Nn / 128; t++) {
        const int s = t & 1;
        const uint32_t k_t = sb + 16384u + (uint32_t)s * 32768u;
        const uint32_t v_t = k_t + 16384u;

        // ---- S' = Q K^T (1-term; S' already in log2 units) ----
        float acc[16][4];
        #pragma unroll
        for (int nt = 0; nt < 16; nt++)
            #pragma unroll
            for (int k = 0; k < 4; k++) acc[nt][k] = 0.0f;

        #pragma unroll
        for (int ks = 0; ks < 4; ks++) {
            #pragma unroll
            for (int pi = 0; pi < 8; pi++) {
                const int key  = pi * 16 + kkey;
                const int unit = 2 * ks + kub;
                const uint32_t off = (uint32_t)(key * 128 + ((unit ^ (key & 7)) << 4));
                uint32_t k_[4];
                ldsm4(k_, k_t + off);
                mma16816(acc[2 * pi],     qf[ks], k_);
                mma16816(acc[2 * pi + 1], qf[ks], k_ + 2);
            }
        }

        // ---- online softmax, base-2 (rows warp-local; 4-lane shfl reduce) ----
        float mx0 = -1e30f, mx1 = -1e30f;
        #pragma unroll
        for (int nt = 0; nt < 16; nt++) {
            mx0 = fmaxf(mx0, fmaxf(acc[nt][0], acc[nt][1]));
            mx1 = fmaxf(mx1, fmaxf(acc[nt][2], acc[nt][3]));
        }
        mx0 = fmaxf(mx0, __shfl_xor_sync(0xffffffffu, mx0, 1));
        mx0 = fmaxf(mx0, __shfl_xor_sync(0xffffffffu, mx0, 2));
        mx1 = fmaxf(mx1, __shfl_xor_sync(0xffffffffu, mx1, 1));
        mx1 = fmaxf(mx1, __shfl_xor_sync(0xffffffffu, mx1, 2));
        const float mn0 = fmaxf(m0, mx0), mn1 = fmaxf(m1, mx1);
        const float a0 = exp2f(m0 - mn0), a1 = exp2f(m1 - mn1);
        m0 = mn0; m1 = mn1;
        float s0 = 0.0f, s1 = 0.0f;
        #pragma unroll
        for (int nt = 0; nt < 16; nt++) {
            acc[nt][0] = exp2f(acc[nt][0] - mn0);
            acc[nt][1] = exp2f(acc[nt][1] - mn0);
            acc[nt][2] = exp2f(acc[nt][2] - mn1);
            acc[nt][3] = exp2f(acc[nt][3] - mn1);
            s0 += acc[nt][0] + acc[nt][1];
            s1 += acc[nt][2] + acc[nt][3];
        }
        s0 += __shfl_xor_sync(0xffffffffu, s0, 1);
        s0 += __shfl_xor_sync(0xffffffffu, s0, 2);
        s1 += __shfl_xor_sync(0xffffffffu, s1, 1);
        s1 += __shfl_xor_sync(0xffffffffu, s1, 2);
        l0 = l0 * a0 + s0;
        l1 = l1 * a1 + s1;
        #pragma unroll
        for (int j = 0; j < 8; j++) {
            o[j][0] *= a0; o[j][1] *= a0;
            o[j][2] *= a1; o[j][3] *= a1;
        }

        // ---- O += P V (1-term; P packed plain fp16, C-frag -> A-frag) ----
        #pragma unroll
        for (int kt = 0; kt < 8; kt++) {
            uint32_t ph[4];
            ph[0] = pack2h(acc[2 * kt][0],     acc[2 * kt][1]);
            ph[1] = pack2h(acc[2 * kt][2],     acc[2 * kt][3]);
            ph[2] = pack2h(acc[2 * kt + 1][0], acc[2 * kt + 1][1]);
            ph[3] = pack2h(acc[2 * kt + 1][2], acc[2 * kt + 1][3]);
            #pragma unroll
            for (int dn = 0; dn < 4; dn++) {
                const int key  = kt * 16 + vkey0;
                const int unit = 2 * dn + vub;
                const uint32_t off = (uint32_t)(key * 128 + ((unit ^ (key & 7)) << 4));
                uint32_t v_[4];
                ldsm4t(v_, v_t + off);
                mma16816(o[2 * dn],     ph, v_);
                mma16816(o[2 * dn + 1], ph, v_ + 2);
            }
        }

        __syncthreads();
        if (t + 2 < Nn / 128) { issue_stage(t + 2, s); CP_COMMIT(); }
        if (t < Nn / 128 - 1) {
            if (t + 2 < Nn / 128) { CP_WAIT(1); } else { CP_WAIT(0); }
            __syncthreads();
        }
    }

    // ---- epilogue: normalize, emit plain fp16 for the out-projection ----
    const float inv0 = 1.0f / l0, inv1 = 1.0f / l1;
    const int gr = lane >> 2, tc = lane & 3;
    const size_t row0 = tokQ + wid * 16 + gr;
    const size_t row1 = row0 + 8;
    #pragma unroll
    for (int nt = 0; nt < 8; nt++) {
        const int d = colOff + nt * 8 + 2 * tc;
        *(uint32_t*)(g_o + row0 * Cc + d) = pack2h(o[nt][0] * inv0, o[nt][1] * inv0);
        *(uint32_t*)(g_o + row1 * Cc + d) = pack2h(o[nt][2] * inv1, o[nt][3] * inv1);
    }
}

// ---------------------------------------------------------------------------
// kernel_launch
// ---------------------------------------------------------------------------
extern "C" void kernel_launch(void* const* d_in, const int* in_sizes, int n_in,
                              void* d_out, int out_size) {
    const float* x  = (const float*)d_in[0];
    const float* Wq = (const float*)d_in[1];
    const float* bq = (const float*)d_in[2];
    const float* Wk = (const float*)d_in[3];
    const float* bk = (const float*)d_in[4];
    const float* Wv = (const float*)d_in[5];
    const float* bv = (const float*)d_in[6];
    const float* Wo = (const float*)d_in[7];
    const float* bo = (const float*)d_in[8];
    float* out = (float*)d_out;

    fp16 *xp, *qp, *kp, *vp, *op, *wt;
    cudaGetSymbolAddress((void**)&xp, g_x);
    cudaGetSymbolAddress((void**)&qp, g_q);
    cudaGetSymbolAddress((void**)&kp, g_k);
    cudaGetSymbolAddress((void**)&vp, g_v);
    cudaGetSymbolAddress((void**)&op, g_o);
    cudaGetSymbolAddress((void**)&wt, g_wt);

    cudaFuncSetAttribute(mma_gemm_qkv, cudaFuncAttributeMaxDynamicSharedMemorySize, GEMM_SMEM);
    cudaFuncSetAttribute(mma_gemm_out, cudaFuncAttributeMaxDynamicSharedMemorySize, GEMM_SMEM);
    cudaFuncSetAttribute(attn_mma, cudaFuncAttributeMaxDynamicSharedMemorySize, ATT_SMEM);

    // x -> plain fp16 (MLP=4 grid-stride)
    {
        const int n4 = Mm * Cc / 4;                 // 2M float4s
        const int blocks = (n4 / 4 + 255) / 256;    // 2048
        conv_h<<<blocks, 256>>>(x, xp, n4);
    }
    // all 4 weight transposes in one launch (z selects matrix)
    {
        W4 ws;
        ws.w[0] = Wq; ws.w[1] = Wk; ws.w[2] = Wv; ws.w[3] = Wo;
        dim3 gW(Cc / 32, Cc / 32, 4), bWt(32, 8);
        conv_wt4<<<gW, bWt>>>(ws, wt);
    }

    // fused QKV projection (single launch, 768 CTAs)
    dim3 gQKV(3 * Cc / 256, Mm / 128);   // (12, 64)
    mma_gemm_qkv<<<gQKV, 256, GEMM_SMEM>>>(xp, wt, bq, bk, bv, qp, kp, vp);

    // tensor-core flash attention -> g_o (plain fp16)
    dim3 gA(Nn / 128, Bb * Hh);          // (16, 64)
    attn_mma<<<gA, 256, ATT_SMEM>>>(qp, kp, vp);

    // output projection -> fp32 out
    dim3 gG(Cc / 256, Mm / 128);         // (4, 64)
    mma_gemm_out<<<gG, 256, GEMM_SMEM>>>(op, wt + 3 * (size_t)Cc * Cc, bo, out);
}

// round 15
// speedup vs baseline: 1.0342x; 1.0342x over previous
#include <cuda_runtime.h>
#include <cuda_fp16.h>
#include <cstdint>

using fp16 = __half;

// Problem constants (fixed by reference)
constexpr int Bb = 4;
constexpr int Nn = 2048;
constexpr int Cc = 1024;
constexpr int Hh = 16;
constexpr int Dd = 64;
constexpr int Mm = Bb * Nn;   // 8192 tokens

// Q pre-scale: 1/sqrt(D) * log2(e)  (softmax done in base-2)
#define SCALE_Q 0.1803368801111204f

// Scratch (allocation-free rule: static device globals)
__device__ fp16 g_x [Mm * Cc];
__device__ fp16 g_q [Mm * Cc];
__device__ fp16 g_k [Mm * Cc];
__device__ fp16 g_v [Mm * Cc];
__device__ fp16 g_o [Mm * Cc];
__device__ fp16 g_wt[4][Cc * Cc];   // W^T [N,K] fp16 (q,k,v contiguous, then o)

// ---------------------------------------------------------------------------
// Portable (sm_100 non-'a') tensor-core helpers
// ---------------------------------------------------------------------------
__device__ __forceinline__ uint32_t smem_u32(const void* p) {
    uint32_t a;
    asm("{ .reg .u64 t; cvta.to.shared.u64 t, %1; cvt.u32.u64 %0, t; }"
        : "=r"(a) : "l"(p));
    return a;
}

__device__ __forceinline__ void mma16816(float* c, const uint32_t* a, const uint32_t* b) {
    asm volatile(
        "mma.sync.aligned.m16n8k16.row.col.f32.f16.f16.f32 "
        "{%0,%1,%2,%3}, {%4,%5,%6,%7}, {%8,%9}, {%0,%1,%2,%3};"
        : "+f"(c[0]), "+f"(c[1]), "+f"(c[2]), "+f"(c[3])
        : "r"(a[0]), "r"(a[1]), "r"(a[2]), "r"(a[3]), "r"(b[0]), "r"(b[1]));
}

__device__ __forceinline__ void ldsm4(uint32_t* r, uint32_t addr) {
    asm volatile("ldmatrix.sync.aligned.m8n8.x4.shared.b16 {%0,%1,%2,%3}, [%4];"
                 : "=r"(r[0]), "=r"(r[1]), "=r"(r[2]), "=r"(r[3]) : "r"(addr));
}

__device__ __forceinline__ void ldsm4t(uint32_t* r, uint32_t addr) {
    asm volatile("ldmatrix.sync.aligned.m8n8.x4.trans.shared.b16 {%0,%1,%2,%3}, [%4];"
                 : "=r"(r[0]), "=r"(r[1]), "=r"(r[2]), "=r"(r[3]) : "r"(addr));
}

__device__ __forceinline__ void cp16(uint32_t dst, const void* src) {
    asm volatile("cp.async.cg.shared.global [%0], [%1], 16;" :: "r"(dst), "l"(src));
}
#define CP_COMMIT() asm volatile("cp.async.commit_group;" ::: "memory")
#define CP_WAIT(n)  asm volatile("cp.async.wait_group %0;" :: "n"(n) : "memory")

__device__ __forceinline__ uint32_t pack2h(float a, float b) {
    __half2 t = __floats2half2_rn(a, b);
    return *(uint32_t*)&t;
}

// ---------------------------------------------------------------------------
// Conversion kernels
// ---------------------------------------------------------------------------
// x fp32 -> fp16, grid-stride with 4 independent float4s/thread (MLP=4).
__global__ void conv_h(const float* __restrict__ in, fp16* __restrict__ out, int n4) {
    const int i0 = blockIdx.x * blockDim.x + threadIdx.x;
    const int stride = gridDim.x * blockDim.x;
    #pragma unroll
    for (int j = 0; j < 4; j++) {
        const int idx = i0 + j * stride;
        if (idx < n4) {
            float4 v = ((const float4*)in)[idx];
            ((uint32_t*)out)[idx * 2    ] = pack2h(v.x, v.y);
            ((uint32_t*)out)[idx * 2 + 1] = pack2h(v.z, v.w);
        }
    }
}

// All four W [K,N] -> WT [N,K] fp16 in ONE launch (blockIdx.z selects matrix).
struct W4 { const float* w[4]; };
__global__ void conv_wt4(W4 ws, fp16* __restrict__ th_base) {
    __shared__ float t[32][33];
    const float* W = ws.w[blockIdx.z];
    fp16* th = th_base + (size_t)blockIdx.z * Cc * Cc;
    const int bx = blockIdx.x, by = blockIdx.y;
    const int tx = threadIdx.x, ty0 = threadIdx.y;  // 32 x 8
    #pragma unroll
    for (int i = 0; i < 32; i += 8)
        t[ty0 + i][tx] = W[(size_t)(by * 32 + ty0 + i) * Cc + bx * 32 + tx];
    __syncthreads();
    #pragma unroll
    for (int i = 0; i < 32; i += 8) {
        float v = t[tx][ty0 + i];
        th[(size_t)(bx * 32 + ty0 + i) * Cc + by * 32 + tx] = __float2half_rn(v);
    }
}

// ---------------------------------------------------------------------------
// GEMM tiling constants (shared by both GEMM kernels)
// CTA tile 128x256, K-chunk 64, 2-stage cp.async double buffer, 8 warps.
// Rows: 64 fp16 = 128B; 16B-unit swizzle u^(row&7).
// ---------------------------------------------------------------------------
constexpr int KC        = 64;
constexpr int NCHUNK    = Cc / KC;        // 16
constexpr int A_TILE_B  = 128 * 128;      // 16KB
constexpr int B_TILE_B  = 256 * 128;      // 32KB
constexpr int STAGE_B   = A_TILE_B + B_TILE_B;   // 49152
constexpr int GEMM_SMEM = 2 * STAGE_B;    // 98304

#define GEMM_MAINLOOP(Aptr, Bptr)                                              \
    const int r0 = tid >> 3, u = tid & 7;                                      \
    const uint32_t du = (uint32_t)((u ^ (r0 & 7)) << 4);                       \
    const fp16* aPb = (Aptr) + (size_t)(m0 + r0) * Cc + u * 8;                 \
    const fp16* bPb = (Bptr) + (size_t)(n0 + r0) * Cc + u * 8;                 \
    const uint32_t aDb = (uint32_t)(r0 * 128) + du;                            \
    const uint32_t bDb = (uint32_t)(A_TILE_B + r0 * 128) + du;                 \
    const int r7  = lane & 7;                                                  \
    const int auh = lane >> 4;                                                 \
    const int buh = (lane >> 3) & 1;                                           \
    uint32_t aoff[4], boff[4];                                                 \
    _Pragma("unroll")                                                          \
    for (int mi = 0; mi < 4; mi++)                                             \
        aoff[mi] = (uint32_t)((wm * 64 + mi * 16 + (lane & 15)) * 128);        \
    _Pragma("unroll")                                                          \
    for (int pi = 0; pi < 4; pi++)                                             \
        boff[pi] = (uint32_t)(A_TILE_B +                                       \
            (wn * 64 + pi * 16 + ((lane >> 4) << 3) + (lane & 7)) * 128);      \
    float acc[4][8][4];                                                        \
    _Pragma("unroll")                                                          \
    for (int mi = 0; mi < 4; mi++)                                             \
        _Pragma("unroll")                                                      \
        for (int ni = 0; ni < 8; ni++)                                         \
            _Pragma("unroll")                                                  \
            for (int k = 0; k < 4; k++) acc[mi][ni][k] = 0.0f;                 \
    auto load_chunk = [&](int c, int s) {                                      \
        const uint32_t stg = sbase + (uint32_t)(s * STAGE_B);                  \
        const int koff = c * KC;                                               \
        const fp16* ap = aPb + koff;                                           \
        _Pragma("unroll")                                                      \
        for (int i = 0; i < 4; i++)                                            \
            cp16(stg + aDb + (uint32_t)(i * 4096), ap + (size_t)i * 32 * Cc);  \
        const fp16* bp = bPb + koff;                                           \
        _Pragma("unroll")                                                      \
        for (int i = 0; i < 8; i++)                                            \
            cp16(stg + bDb + (uint32_t)(i * 4096), bp + (size_t)i * 32 * Cc);  \
    };                                                                         \
    load_chunk(0, 0); CP_COMMIT();                                             \
    for (int c = 0; c < NCHUNK; c++) {                                         \
        const int s = c & 1;                                                   \
        if (c + 1 < NCHUNK) {                                                  \
            load_chunk(c + 1, s ^ 1);                                          \
            CP_COMMIT();                                                       \
            CP_WAIT(1);                                                        \
        } else {                                                               \
            CP_WAIT(0);                                                        \
        }                                                                      \
        __syncthreads();                                                       \
        const uint32_t sS = sbase + (uint32_t)(s * STAGE_B);                   \
        _Pragma("unroll")                                                      \
        for (int ks = 0; ks < 4; ks++) {                                       \
            uint32_t a_[4][4], b_[4][4];                                       \
            const uint32_t uh = (uint32_t)(ks << 1);                           \
            _Pragma("unroll")                                                  \
            for (int mi = 0; mi < 4; mi++)                                     \
                ldsm4(a_[mi], sS + aoff[mi] + (((uh + auh) ^ r7) << 4));       \
            _Pragma("unroll")                                                  \
            for (int pi = 0; pi < 4; pi++)                                     \
                ldsm4(b_[pi], sS + boff[pi] + (((uh + buh) ^ r7) << 4));       \
            _Pragma("unroll")                                                  \
            for (int mi = 0; mi < 4; mi++)                                     \
                _Pragma("unroll")                                              \
                for (int ni = 0; ni < 8; ni++)                                 \
                    mma16816(acc[mi][ni], a_[mi], &b_[ni >> 1][(ni & 1) * 2]); \
        }                                                                      \
        __syncthreads();                                                       \
    }

// ---------------------------------------------------------------------------
// Fused QKV projection: one launch, grid (12, 64). B = concatenated
// [Wq^T; Wk^T; Wv^T] (3072 x 1024). Sector (bx>>2) routes output to q/k/v.
// Q is pre-scaled by SCALE_Q (1/sqrt(D) * log2e) for base-2 softmax.
// ---------------------------------------------------------------------------
__global__ __launch_bounds__(256, 1)
void mma_gemm_qkv(const fp16* __restrict__ A, const fp16* __restrict__ B3,
                  const float* __restrict__ bq, const float* __restrict__ bk,
                  const float* __restrict__ bv,
                  fp16* __restrict__ qp, fp16* __restrict__ kp, fp16* __restrict__ vp) {
    extern __shared__ char smem[];
    const uint32_t sbase = smem_u32(smem);
    const int tid  = threadIdx.x;
    const int lane = tid & 31;
    const int wid  = tid >> 5;
    const int m0 = blockIdx.y * 128;
    const int n0 = blockIdx.x * 256;          // global row in [0, 3072)
    const int wm = wid & 1;
    const int wn = wid >> 1;

    const int sector = blockIdx.x >> 2;       // 0=q, 1=k, 2=v
    const int n0l    = n0 & 1023;             // column base within the 1024-wide output
    fp16* OH = (sector == 0) ? qp : (sector == 1) ? kp : vp;
    const float* bias = (sector == 0) ? bq : (sector == 1) ? bk : bv;
    const float scale = (sector == 0) ? SCALE_Q : 1.0f;

    GEMM_MAINLOOP(A, B3)

    // ---- epilogue: + bias, x scale, fp16 out ----
    const int group = lane >> 2, tig = lane & 3;
    #pragma unroll
    for (int mi = 0; mi < 4; mi++) {
        const int r = m0 + wm * 64 + mi * 16 + group;
        #pragma unroll
        for (int ni = 0; ni < 8; ni++) {
            const int col = n0l + wn * 64 + ni * 8 + tig * 2;
            const float b0 = bias[col], b1 = bias[col + 1];
            *(uint32_t*)(OH + (size_t)r * Cc + col) =
                pack2h((acc[mi][ni][0] + b0) * scale, (acc[mi][ni][1] + b1) * scale);
            *(uint32_t*)(OH + (size_t)(r + 8) * Cc + col) =
                pack2h((acc[mi][ni][2] + b0) * scale, (acc[mi][ni][3] + b1) * scale);
        }
    }
}

// ---------------------------------------------------------------------------
// Output projection: fp16 A x fp16 B^T -> fp32 C + bias.
// ---------------------------------------------------------------------------
__global__ __launch_bounds__(256, 1)
void mma_gemm_out(const fp16* __restrict__ A, const fp16* __restrict__ B,
                  const float* __restrict__ bias, float* __restrict__ C) {
    extern __shared__ char smem[];
    const uint32_t sbase = smem_u32(smem);
    const int tid  = threadIdx.x;
    const int lane = tid & 31;
    const int wid  = tid >> 5;
    const int m0 = blockIdx.y * 128;
    const int n0 = blockIdx.x * 256;
    const int wm = wid & 1;
    const int wn = wid >> 1;

    GEMM_MAINLOOP(A, B)

    const int group = lane >> 2, tig = lane & 3;
    #pragma unroll
    for (int mi = 0; mi < 4; mi++) {
        const int r = m0 + wm * 64 + mi * 16 + group;
        #pragma unroll
        for (int ni = 0; ni < 8; ni++) {
            const int col = n0 + wn * 64 + ni * 8 + tig * 2;
            const float b0 = bias[col], b1 = bias[col + 1];
            *(float2*)(C + (size_t)r * Cc + col) =
                make_float2(acc[mi][ni][0] + b0, acc[mi][ni][1] + b1);
            *(float2*)(C + (size_t)(r + 8) * Cc + col) =
                make_float2(acc[mi][ni][2] + b0, acc[mi][ni][3] + b1);
        }
    }
}

// ---------------------------------------------------------------------------
// Tensor-core flash attention, plain fp16 1-term, base-2 softmax.
// CTA = 64-row Q tile of one (b,h); 128 threads (4 warps x 16 S-rows each);
// __launch_bounds__(128, 2) -> 2 CTAs/SM so one CTA's softmax overlaps the
// other's MMAs (R14 profile: tensor=50.9% at occ 1 CTA).
// Smem: Q (8KB) + 2 stages x (K|V) (64KB) = 72KB; 2 CTAs = 144KB < 228KB.
// All rows 64 fp16 = 128B, unit swizzle u^(row&7).
// ---------------------------------------------------------------------------
constexpr int ATT_SMEM = 8192 + 2 * 32768;   // 73728

__global__ __launch_bounds__(128, 2)
void attn_mma(const fp16* __restrict__ Q,
              const fp16* __restrict__ K, const fp16* __restrict__ V) {
    extern __shared__ char smem[];
    const uint32_t sb = smem_u32(smem);
    const int tid  = threadIdx.x;
    const int lane = tid & 31;
    const int wid  = tid >> 5;          // 0..3
    const int bh = blockIdx.y;
    const int b  = bh >> 4;
    const int h  = bh & 15;
    const int q0 = blockIdx.x * 64;
    const size_t tokQ = (size_t)(b * Nn + q0);
    const size_t tokK = (size_t)(b * Nn);
    const int colOff = h * Dd;

    // -- async load Q (64 rows x 8 units = 512 units over 128 threads) --
    #pragma unroll
    for (int i = 0; i < 4; i++) {
        const int idx = tid + i * 128;
        const int r = idx >> 3, u = idx & 7;
        cp16(sb + r * 128 + ((u ^ (r & 7)) << 4),
             Q + (tokQ + r) * Cc + colOff + u * 8);
    }

    auto issue_stage = [&](int t, int s) {
        const uint32_t stg = sb + 8192u + (uint32_t)s * 32768u;
        const size_t tokT = tokK + (size_t)t * 128;
        #pragma unroll
        for (int i = 0; i < 16; i++) {
            const int idx = tid + i * 128;
            const int tile = idx >> 10, rem = idx & 1023;
            const int r = rem >> 3, u = rem & 7;
            const fp16* base = tile ? V : K;
            cp16(stg + tile * 16384 + r * 128 + ((u ^ (r & 7)) << 4),
                 base + (tokT + r) * Cc + colOff + u * 8);
        }
    };

    issue_stage(0, 0); CP_COMMIT();   // group0 = Q + stage0
    issue_stage(1, 1); CP_COMMIT();   // group1 = stage1
    CP_WAIT(1);
    __syncthreads();

    // -- hoist Q fragments (loop-invariant) --
    const int qrow  = wid * 16 + (lane & 15);
    const uint32_t qso = (uint32_t)(qrow * 128);
    uint32_t qf[4][4];
    #pragma unroll
    for (int ks = 0; ks < 4; ks++) {
        const int unit = 2 * ks + (lane >> 4);
        ldsm4(qf[ks], sb + qso + (uint32_t)(((unit ^ (qrow & 7))) << 4));
    }

    float m0 = -1e30f, m1 = -1e30f, l0 = 0.0f, l1 = 0.0f;
    float o[8][4];
    #pragma unroll
    for (int j = 0; j < 8; j++)
        #pragma unroll
        for (int k = 0; k < 4; k++) o[j][k] = 0.0f;

    const int kkey  = ((lane >> 4) << 3) + (lane & 7);
    const int kub   = (lane >> 3) & 1;
    const int vkey0 = lane & 15;
    const int vub   = lane >> 4;

    for (int t = 0; t < Nn / 128; t++) {
        const int s = t & 1;
        const uint32_t k_t = sb + 8192u + (uint32_t)s * 32768u;
        const uint32_t v_t = k_t + 16384u;

        // ---- S' = Q K^T (1-term; S' already in log2 units) ----
        float acc[16][4];
        #pragma unroll
        for (int nt = 0; nt < 16; nt++)
            #pragma unroll
            for (int k = 0; k < 4; k++) acc[nt][k] = 0.0f;

        #pragma unroll
        for (int ks = 0; ks < 4; ks++) {
            #pragma unroll
            for (int pi = 0; pi < 8; pi++) {
                const int key  = pi * 16 + kkey;
                const int unit = 2 * ks + kub;
                const uint32_t off = (uint32_t)(key * 128 + ((unit ^ (key & 7)) << 4));
                uint32_t k_[4];
                ldsm4(k_, k_t + off);
                mma16816(acc[2 * pi],     qf[ks], k_);
                mma16816(acc[2 * pi + 1], qf[ks], k_ + 2);
            }
        }

        // ---- online softmax, base-2 (rows warp-local; 4-lane shfl reduce) ----
        float mx0 = -1e30f, mx1 = -1e30f;
        #pragma unroll
        for (int nt = 0; nt < 16; nt++) {
            mx0 = fmaxf(mx0, fmaxf(acc[nt][0], acc[nt][1]));
            mx1 = fmaxf(mx1, fmaxf(acc[nt][2], acc[nt][3]));
        }
        mx0 = fmaxf(mx0, __shfl_xor_sync(0xffffffffu, mx0, 1));
        mx0 = fmaxf(mx0, __shfl_xor_sync(0xffffffffu, mx0, 2));
        mx1 = fmaxf(mx1, __shfl_xor_sync(0xffffffffu, mx1, 1));
        mx1 = fmaxf(mx1, __shfl_xor_sync(0xffffffffu, mx1, 2));
        const float mn0 = fmaxf(m0, mx0), mn1 = fmaxf(m1, mx1);
        const float a0 = exp2f(m0 - mn0), a1 = exp2f(m1 - mn1);
        m0 = mn0; m1 = mn1;
        float s0 = 0.0f, s1 = 0.0f;
        #pragma unroll
        for (int nt = 0; nt < 16; nt++) {
            acc[nt][0] = exp2f(acc[nt][0] - mn0);
            acc[nt][1] = exp2f(acc[nt][1] - mn0);
            acc[nt][2] = exp2f(acc[nt][2] - mn1);
            acc[nt][3] = exp2f(acc[nt][3] - mn1);
            s0 += acc[nt][0] + acc[nt][1];
            s1 += acc[nt][2] + acc[nt][3];
        }
        s0 += __shfl_xor_sync(0xffffffffu, s0, 1);
        s0 += __shfl_xor_sync(0xffffffffu, s0, 2);
        s1 += __shfl_xor_sync(0xffffffffu, s1, 1);
        s1 += __shfl_xor_sync(0xffffffffu, s1, 2);
        l0 = l0 * a0 + s0;
        l1 = l1 * a1 + s1;
        #pragma unroll
        for (int j = 0; j < 8; j++) {
            o[j][0] *= a0; o[j][1] *= a0;
            o[j][2] *= a1; o[j][3] *= a1;
        }

        // ---- O += P V (1-term; P packed plain fp16, C-frag -> A-frag) ----
        #pragma unroll
        for (int kt = 0; kt < 8; kt++) {
            uint32_t ph[4];
            ph[0] = pack2h(acc[2 * kt][0],     acc[2 * kt][1]);
            ph[1] = pack2h(acc[2 * kt][2],     acc[2 * kt][3]);
            ph[2] = pack2h(acc[2 * kt + 1][0], acc[2 * kt + 1][1]);
            ph[3] = pack2h(acc[2 * kt + 1][2], acc[2 * kt + 1][3]);
            #pragma unroll
            for (int dn = 0; dn < 4; dn++) {
                const int key  = kt * 16 + vkey0;
                const int unit = 2 * dn + vub;
                const uint32_t off = (uint32_t)(key * 128 + ((unit ^ (key & 7)) << 4));
                uint32_t v_[4];
                ldsm4t(v_, v_t + off);
                mma16816(o[2 * dn],     ph, v_);
                mma16816(o[2 * dn + 1], ph, v_ + 2);
            }
        }

        __syncthreads();
        if (t + 2 < Nn / 128) { issue_stage(t + 2, s); CP_COMMIT(); }
        if (t < Nn / 128 - 1) {
            if (t + 2 < Nn / 128) { CP_WAIT(1); } else { CP_WAIT(0); }
            __syncthreads();
        }
    }

    // ---- epilogue: normalize, emit plain fp16 for the out-projection ----
    const float inv0 = 1.0f / l0, inv1 = 1.0f / l1;
    const int gr = lane >> 2, tc = lane & 3;
    const size_t row0 = tokQ + wid * 16 + gr;
    const size_t row1 = row0 + 8;
    #pragma unroll
    for (int nt = 0; nt < 8; nt++) {
        const int d = colOff + nt * 8 + 2 * tc;
        *(uint32_t*)(g_o + row0 * Cc + d) = pack2h(o[nt][0] * inv0, o[nt][1] * inv0);
        *(uint32_t*)(g_o + row1 * Cc + d) = pack2h(o[nt][2] * inv1, o[nt][3] * inv1);
    }
}

// ---------------------------------------------------------------------------
// kernel_launch
// ---------------------------------------------------------------------------
extern "C" void kernel_launch(void* const* d_in, const int* in_sizes, int n_in,
                              void* d_out, int out_size) {
    const float* x  = (const float*)d_in[0];
    const float* Wq = (const float*)d_in[1];
    const float* bq = (const float*)d_in[2];
    const float* Wk = (const float*)d_in[3];
    const float* bk = (const float*)d_in[4];
    const float* Wv = (const float*)d_in[5];
    const float* bv = (const float*)d_in[6];
    const float* Wo = (const float*)d_in[7];
    const float* bo = (const float*)d_in[8];
    float* out = (float*)d_out;

    fp16 *xp, *qp, *kp, *vp, *op, *wt;
    cudaGetSymbolAddress((void**)&xp, g_x);
    cudaGetSymbolAddress((void**)&qp, g_q);
    cudaGetSymbolAddress((void**)&kp, g_k);
    cudaGetSymbolAddress((void**)&vp, g_v);
    cudaGetSymbolAddress((void**)&op, g_o);
    cudaGetSymbolAddress((void**)&wt, g_wt);

    cudaFuncSetAttribute(mma_gemm_qkv, cudaFuncAttributeMaxDynamicSharedMemorySize, GEMM_SMEM);
    cudaFuncSetAttribute(mma_gemm_out, cudaFuncAttributeMaxDynamicSharedMemorySize, GEMM_SMEM);
    cudaFuncSetAttribute(attn_mma, cudaFuncAttributeMaxDynamicSharedMemorySize, ATT_SMEM);

    // x -> plain fp16 (MLP=4 grid-stride)
    {
        const int n4 = Mm * Cc / 4;                 // 2M float4s
        const int blocks = (n4 / 4 + 255) / 256;    // 2048
        conv_h<<<blocks, 256>>>(x, xp, n4);
    }
    // all 4 weight transposes in one launch (z selects matrix)
    {
        W4 ws;
        ws.w[0] = Wq; ws.w[1] = Wk; ws.w[2] = Wv; ws.w[3] = Wo;
        dim3 gW(Cc / 32, Cc / 32, 4), bWt(32, 8);
        conv_wt4<<<gW, bWt>>>(ws, wt);
    }

    // fused QKV projection (single launch, 768 CTAs)
    dim3 gQKV(3 * Cc / 256, Mm / 128);   // (12, 64)
    mma_gemm_qkv<<<gQKV, 256, GEMM_SMEM>>>(xp, wt, bq, bk, bv, qp, kp, vp);

    // tensor-core flash attention -> g_o (plain fp16), 2 CTAs/SM
    dim3 gA(Nn / 64, Bb * Hh);           // (32, 64)
    attn_mma<<<gA, 128, ATT_SMEM>>>(qp, kp, vp);

    // output projection -> fp32 out
    dim3 gG(Cc / 256, Mm / 128);         // (4, 64)
    mma_gemm_out<<<gG, 256, GEMM_SMEM>>>(op, wt + 3 * (size_t)Cc * Cc, bo, out);
}